// round 15
// baseline (speedup 1.0000x reference)
#include <cuda_runtime.h>
#include <cstdint>

#define N_ATOMS  200000
#define N_FEAT   1024
#define N_STRUCT 2000
#define NTHREADS 512
#define M_TILE   128
#define CHUNKS1  16      // K=1024 / 64
#define CHUNKS2  4       // K=256  / 64

// ---- SMEM layout (bytes). fp16 operand tiles, rows padded to 144B (64k + 8 pad halves)
#define A_ROW_B    144
#define B_ROW_B    144
#define H1_ROW_B   528                   // 256 + 8 pad halves
#define A_BUF_B    18432                 // 128*144
#define B_BUF_B    36864                 // 256*144
#define OFF_B      0                     // 2 bufs -> 73728
#define OFF_A      73728                 // 2 bufs 36864, aliased inside h1 region
#define OFF_H1     73728                 // 128*528 = 67584 -> ends 141312
#define OFF_WPSL   141312                // 4096
#define OFF_WOUT   145408                // 1024
#define OFF_SATOM  146432                // 512
#define OFF_MBAR   146944                // 6 x 8B: A0 A1 B0 B1 F0 F1
#define SMEM_BYTES 147008

// weights pre-converted to fp16 (rn), natural [n][k] layout, packed as uint32 pairs
__device__ __align__(16) uint32_t g_W1h[256 * 1024 / 2];
__device__ __align__(16) uint32_t g_W2h[256 * 256 / 2];

__device__ __forceinline__ uint32_t pack_f16x2(float lo, float hi) {
    uint32_t r;
    asm("cvt.rn.f16x2.f32 %0, %1, %2;" : "=r"(r) : "f"(hi), "f"(lo));
    return r;
}

__device__ __forceinline__ void mma_f16(float c[4], const uint32_t a[4], uint32_t b0, uint32_t b1) {
    asm volatile(
        "mma.sync.aligned.m16n8k16.row.col.f32.f16.f16.f32 "
        "{%0,%1,%2,%3}, {%4,%5,%6,%7}, {%8,%9}, {%0,%1,%2,%3};\n"
        : "+f"(c[0]), "+f"(c[1]), "+f"(c[2]), "+f"(c[3])
        : "r"(a[0]), "r"(a[1]), "r"(a[2]), "r"(a[3]), "r"(b0), "r"(b1));
}

#define LDM_X4(r, a) \
    asm volatile("ldmatrix.sync.aligned.m8n8.x4.shared.b16 {%0,%1,%2,%3}, [%4];" \
        : "=r"((r)[0]), "=r"((r)[1]), "=r"((r)[2]), "=r"((r)[3]) : "r"(a))

__device__ __forceinline__ void cp_async16(uint32_t saddr, const void* gptr) {
    asm volatile("cp.async.cg.shared.global [%0], [%1], 16;\n" :: "r"(saddr), "l"(gptr));
}
__device__ __forceinline__ void cp_commit() { asm volatile("cp.async.commit_group;\n"); }
__device__ __forceinline__ void cp_wait0()  { asm volatile("cp.async.wait_group 0;\n" ::: "memory"); }

// ---- mbarrier helpers ----
#define MBAR_INIT(a, c) \
    asm volatile("mbarrier.init.shared.b64 [%0], %1;" :: "r"(a), "r"(c) : "memory")

__device__ __forceinline__ void mbar_arrive(uint32_t a) {
    asm volatile("mbarrier.arrive.shared.b64 _, [%0];" :: "r"(a) : "memory");
}
// .noinc REQUIRED (R10 hang: non-noinc bumps the expected count first)
__device__ __forceinline__ void cpasync_mbar_arrive(uint32_t a) {
    asm volatile("cp.async.mbarrier.arrive.noinc.shared.b64 [%0];" :: "r"(a) : "memory");
}

#define MBAR_WAIT(mb, ph) do { \
    uint32_t _m = (mb), _p = (ph), _d; \
    asm volatile("{ .reg .pred p; mbarrier.try_wait.parity.acquire.cta.shared::cta.b64 p, [%1], %2; selp.b32 %0, 1, 0, p; }" \
        : "=r"(_d) : "r"(_m), "r"(_p) : "memory"); \
    if (!_d) { \
        asm volatile("{ .reg .pred P1; WL_%=: mbarrier.try_wait.parity.acquire.cta.shared::cta.b64 P1, [%0], %1, 0x989680; @P1 bra.uni WD_%=; bra.uni WL_%=; WD_%=: }" \
            :: "r"(_m), "r"(_p) : "memory"); \
    } } while (0)

__device__ __forceinline__ float silu(float x) { return x / (1.0f + __expf(-x)); }

// setup: zero out + convert weights (one launch)
__global__ void setup_kernel(const float* __restrict__ W1,
                             const float* __restrict__ W2,
                             float* __restrict__ out, int n_out) {
    int i = blockIdx.x * blockDim.x + threadIdx.x;
    if (i < n_out) out[i] = 0.0f;
    if (i < 256 * 1024 / 2) g_W1h[i] = pack_f16x2(W1[2 * i], W1[2 * i + 1]);
    if (i < 256 * 256 / 2)  g_W2h[i] = pack_f16x2(W2[2 * i], W2[2 * i + 1]);
}

__global__ void __launch_bounds__(NTHREADS, 1)
fused_psm_kernel(const float* __restrict__ ps,
                 const int*   __restrict__ numbers,
                 const int*   __restrict__ batch,
                 const float* __restrict__ Wcomp,
                 const float* __restrict__ Wpsl,
                 const float* __restrict__ Wout,
                 float* __restrict__ out) {
    extern __shared__ char smem[];
    const uint32_t sbase = (uint32_t)__cvta_generic_to_shared(smem);
    float* sWpsl = (float*)(smem + OFF_WPSL);
    float* sWout = (float*)(smem + OFF_WOUT);
    float* sAtom = (float*)(smem + OFF_SATOM);

    const uint32_t mbA = sbase + OFF_MBAR;        // +0, +8
    const uint32_t mbB = sbase + OFF_MBAR + 16;   // +16, +24
    const uint32_t mbF = sbase + OFF_MBAR + 32;   // +32, +40

    const int tid  = threadIdx.x;
    const int lane = tid & 31;
    const int w    = tid >> 5;
    const int g    = lane >> 2;
    const int t    = lane & 3;
    const int wm   = w & 3;    // rows wm*32..+31
    const int wn   = w >> 2;   // cols wn*64..+63
    const long tileBase = (long)blockIdx.x * M_TILE;

    // ldmatrix lane geometry
    const int lr = lane & 7;
    const uint32_t aAddr0 = sbase + OFF_A +
        (uint32_t)((wm * 32 + ((lane >> 3) & 1) * 8 + lr) * A_ROW_B + (lane >> 4) * 16);
    const uint32_t hAddr0 = sbase + OFF_H1 +
        (uint32_t)((wm * 32 + ((lane >> 3) & 1) * 8 + lr) * H1_ROW_B + (lane >> 4) * 16);
    const uint32_t bAddr0 = sbase + OFF_B +
        (uint32_t)((wn * 64 + (lane >> 4) * 8 + lr) * B_ROW_B + ((lane >> 3) & 1) * 16);

    if (tid < 256) sWout[tid] = Wout[tid];
    if (tid == 0) {
#pragma unroll
        for (int i = 0; i < 6; i++) MBAR_INIT(sbase + OFF_MBAR + i * 8, NTHREADS);
    }
    for (int i = tid; i < 1024; i += NTHREADS) sWpsl[i] = Wpsl[i];
    // sWpsl + mbarrier.init must be globally visible before prologue (R6 lesson).
    __syncthreads();

    // producer mapping: thread owns row=tid>>2 (0..127), 16 consecutive k at (tid&3)*16
    const int prow = tid >> 2;
    const int pt4  = tid & 3;
    const bool pvalid = (tileBase + prow) < (long)N_ATOMS;
    const float* pSrc = ps + (tileBase + prow) * (long)N_FEAT + pt4 * 16;
    const uint32_t aStore = sbase + OFF_A + (uint32_t)(prow * A_ROW_B + pt4 * 32);

    float acc[2][8][4];
#pragma unroll
    for (int mt = 0; mt < 2; mt++)
#pragma unroll
        for (int nt = 0; nt < 8; nt++)
#pragma unroll
            for (int c = 0; c < 4; c++) acc[mt][nt][c] = 0.0f;

    float psl = 0.0f;
    float rg[16];

    auto ldg_A = [&](int kc) {
        if (pvalid) {
            const float4* p = (const float4*)(pSrc + kc * 64);
#pragma unroll
            for (int j = 0; j < 4; j++) {
                float4 v = p[j];
                rg[4 * j] = v.x; rg[4 * j + 1] = v.y; rg[4 * j + 2] = v.z; rg[4 * j + 3] = v.w;
            }
        } else {
#pragma unroll
            for (int j = 0; j < 16; j++) rg[j] = 0.0f;
        }
    };
    auto sts_A = [&](int b) {
        uint32_t pk[8];
#pragma unroll
        for (int j = 0; j < 8; j++) pk[j] = pack_f16x2(rg[2 * j], rg[2 * j + 1]);
        uint32_t d = aStore + b * A_BUF_B;
        asm volatile("st.shared.v4.b32 [%0], {%1,%2,%3,%4};" :: "r"(d),
                     "r"(pk[0]), "r"(pk[1]), "r"(pk[2]), "r"(pk[3]));
        asm volatile("st.shared.v4.b32 [%0], {%1,%2,%3,%4};" :: "r"(d + 16),
                     "r"(pk[4]), "r"(pk[5]), "r"(pk[6]), "r"(pk[7]));
    };
    auto psl_acc = [&](int kc) {
        const float* wp = sWpsl + kc * 64 + pt4 * 16;
#pragma unroll
        for (int j = 0; j < 16; j++) psl += rg[j] * wp[j];
    };
    auto load_B1 = [&](int kc, int b) {
#pragma unroll
        for (int j = 0; j < 4; j++) {
            int idx = tid + j * NTHREADS;          // 0..2047
            int row = idx >> 3, c8 = idx & 7;
            uint32_t dst = sbase + OFF_B + b * B_BUF_B + row * B_ROW_B + c8 * 16;
            cp_async16(dst, &g_W1h[row * 512 + kc * 32 + c8 * 4]);
        }
        cp_commit();
    };
    auto load_B2 = [&](int c2, int b) {
#pragma unroll
        for (int j = 0; j < 4; j++) {
            int idx = tid + j * NTHREADS;
            int row = idx >> 3, c8 = idx & 7;
            uint32_t dst = sbase + OFF_B + b * B_BUF_B + row * B_ROW_B + c8 * 16;
            cp_async16(dst, &g_W2h[row * 128 + c2 * 32 + c8 * 4]);
        }
        cp_commit();
    };

    // MMA block for one chunk. bb is double-buffered: the LDSM for group np+1
    // is issued BEFORE the 16 MMAs of group np, hiding ~30cyc LDSM latency
    // behind ~64 tensor cycles (volatile asm pins program order, so ptxas
    // cannot do this reordering itself).
    auto mma_chunk = [&](uint32_t aA, uint32_t bA, int rstride) {
#pragma unroll
        for (int ks = 0; ks < 4; ks++) {
            uint32_t a0[4], a1[4], bb[2][4];
            LDM_X4(a0, aA + ks * 32);
            LDM_X4(a1, aA + ks * 32 + 16 * rstride);
            LDM_X4(bb[0], bA + ks * 32);
#pragma unroll
            for (int np = 0; np < 4; np++) {
                const int cur = np & 1;
                if (np < 3) LDM_X4(bb[cur ^ 1], bA + ks * 32 + (np + 1) * (16 * B_ROW_B));
                mma_f16(acc[0][2 * np],     a0, bb[cur][0], bb[cur][1]);
                mma_f16(acc[0][2 * np + 1], a0, bb[cur][2], bb[cur][3]);
                mma_f16(acc[1][2 * np],     a1, bb[cur][0], bb[cur][1]);
                mma_f16(acc[1][2 * np + 1], a1, bb[cur][2], bb[cur][3]);
            }
        }
    };

    // ---- prologue: chunk 0 staged + signaled; chunk 1 A in regs ----
    ldg_A(0);
    load_B1(0, 0);
    cpasync_mbar_arrive(mbB + 0);      // B(0) ready when this thread's groups land
    sts_A(0);
    mbar_arrive(mbA + 0);              // A(0) stores visible
    psl_acc(0);
    ldg_A(1);

    // =============== GEMM1 (mbarrier pipeline, warps may skew) ===============
    for (int kc = 0; kc < CHUNKS1; kc++) {
        const int buf = kc & 1;
        const int ph  = (kc >> 1) & 1;

        // --- produce chunk kc+1 into buf^1 ---
        if (kc + 1 < CHUNKS1) {
            if (kc + 1 >= 2) {
                // wait until all readers of chunk kc-1 (same buf^1) are done
                MBAR_WAIT(mbF + (buf ^ 1) * 8, (((kc + 1) >> 1) & 1) ^ 1);
            }
            sts_A(buf ^ 1);                       // A(kc+1), regs from prev iter
            mbar_arrive(mbA + (buf ^ 1) * 8);
            psl_acc(kc + 1);
            load_B1(kc + 1, buf ^ 1);
            cpasync_mbar_arrive(mbB + (buf ^ 1) * 8);
            if (kc + 2 < CHUNKS1) ldg_A(kc + 2);
        }

        // --- consume chunk kc ---
        MBAR_WAIT(mbA + buf * 8, ph);
        MBAR_WAIT(mbB + buf * 8, ph);
        mma_chunk(aAddr0 + buf * A_BUF_B, bAddr0 + buf * B_BUF_B, A_ROW_B);
        mbar_arrive(mbF + buf * 8);               // this thread done reading buf
    }
    __syncthreads();   // all GEMM1 reads done before h1 overwrites A alias

    // GEMM2 B chunk 0 prefetch overlaps h1 write
    load_B2(0, 0);

    // psl reduce (4 threads per row share a warp quad)
    psl += __shfl_xor_sync(0xffffffffu, psl, 1);
    psl += __shfl_xor_sync(0xffffffffu, psl, 2);
    if (pt4 == 0) sAtom[prow] = psl;

    // h1 = fp16(silu(acc)) -> row-major SMEM; reset acc
#pragma unroll
    for (int mt = 0; mt < 2; mt++) {
        int row = wm * 32 + mt * 16 + g;
#pragma unroll
        for (int nt = 0; nt < 8; nt++) {
            int col = wn * 64 + nt * 8 + 2 * t;
            *(uint32_t*)(smem + OFF_H1 + row * H1_ROW_B + col * 2) =
                pack_f16x2(silu(acc[mt][nt][0]), silu(acc[mt][nt][1]));
            *(uint32_t*)(smem + OFF_H1 + (row + 8) * H1_ROW_B + col * 2) =
                pack_f16x2(silu(acc[mt][nt][2]), silu(acc[mt][nt][3]));
            acc[mt][nt][0] = acc[mt][nt][1] = acc[mt][nt][2] = acc[mt][nt][3] = 0.0f;
        }
    }

    // =============== GEMM2: acc += h1 x W2^T (simple barrier pipeline) ========
    for (int c = 0; c < CHUNKS2; c++) {
        const int buf = c & 1;
        cp_wait0();
        __syncthreads();   // B2(c) arrived; h1 writes visible (c==0)
        if (c + 1 < CHUNKS2) load_B2(c + 1, buf ^ 1);

        mma_chunk(hAddr0 + c * 128, bAddr0 + buf * B_BUF_B, H1_ROW_B);
    }

    // ---- epilogue: psnn = silu(h2) . Wout ----
#pragma unroll
    for (int mt = 0; mt < 2; mt++) {
        float p0 = 0.0f, p1 = 0.0f;
#pragma unroll
        for (int nt = 0; nt < 8; nt++) {
            int col = wn * 64 + nt * 8 + 2 * t;
            float w0 = sWout[col], w1 = sWout[col + 1];
            p0 += silu(acc[mt][nt][0]) * w0 + silu(acc[mt][nt][1]) * w1;
            p1 += silu(acc[mt][nt][2]) * w0 + silu(acc[mt][nt][3]) * w1;
        }
        p0 += __shfl_xor_sync(0xffffffffu, p0, 1);
        p0 += __shfl_xor_sync(0xffffffffu, p0, 2);
        p1 += __shfl_xor_sync(0xffffffffu, p1, 1);
        p1 += __shfl_xor_sync(0xffffffffu, p1, 2);
        if (t == 0) {
            atomicAdd(&sAtom[wm * 32 + mt * 16 + g], p0);
            atomicAdd(&sAtom[wm * 32 + mt * 16 + 8 + g], p1);
        }
    }
    __syncthreads();

    if (tid < M_TILE) {
        long a = tileBase + tid;
        if (a < N_ATOMS) {
            float v = sAtom[tid] + Wcomp[numbers[a]];
            atomicAdd(&out[batch[a]], v);
        }
    }
}

extern "C" void kernel_launch(void* const* d_in, const int* in_sizes, int n_in,
                              void* d_out, int out_size) {
    const float* ps      = (const float*)d_in[0];
    const int*   numbers = (const int*)  d_in[1];
    const int*   batch   = (const int*)  d_in[2];
    const float* Wcomp   = (const float*)d_in[3];
    const float* Wpsl    = (const float*)d_in[4];
    const float* W1      = (const float*)d_in[5];
    const float* W2      = (const float*)d_in[6];
    const float* Wout    = (const float*)d_in[7];
    float* out = (float*)d_out;

    cudaFuncSetAttribute(fused_psm_kernel,
                         cudaFuncAttributeMaxDynamicSharedMemorySize, SMEM_BYTES);

    setup_kernel<<<(256 * 1024 / 2 + 255) / 256, 256>>>(W1, W2, out, out_size);

    int grid = (N_ATOMS + M_TILE - 1) / M_TILE;  // 1563
    fused_psm_kernel<<<grid, NTHREADS, SMEM_BYTES>>>(
        ps, numbers, batch, Wcomp, Wpsl, Wout, out);
}

// round 16
// speedup vs baseline: 1.6466x; 1.6466x over previous
#include <cuda_runtime.h>
#include <cstdint>

#define N_ATOMS  200000
#define N_FEAT   1024
#define N_STRUCT 2000
#define NTHREADS 512
#define M_TILE   128
#define CHUNKS1  16      // K=1024 / 64
#define CHUNKS2  4       // K=256  / 64

// ---- SMEM layout (bytes). fp16 operand tiles, rows padded to 144B (64k + 8 pad halves)
#define A_ROW_B    144
#define B_ROW_B    144
#define H1_ROW_B   528                   // 256 + 8 pad halves
#define A_BUF_B    18432                 // 128*144
#define B_BUF_B    36864                 // 256*144
#define OFF_B      0                     // 2 bufs -> 73728
#define OFF_A      73728                 // 2 bufs 36864, aliased inside h1 region
#define OFF_H1     73728                 // 128*528 = 67584 -> ends 141312
#define OFF_WPSL   141312                // 4096
#define OFF_WOUT   145408                // 1024
#define OFF_SATOM  146432                // 512
#define OFF_MBAR   146944                // 4 x 8B: R0 R1 F0 F1
#define SMEM_BYTES 147008

// weights pre-converted to fp16 (rn), natural [n][k] layout, packed as uint32 pairs
__device__ __align__(16) uint32_t g_W1h[256 * 1024 / 2];
__device__ __align__(16) uint32_t g_W2h[256 * 256 / 2];

__device__ __forceinline__ uint32_t pack_f16x2(float lo, float hi) {
    uint32_t r;
    asm("cvt.rn.f16x2.f32 %0, %1, %2;" : "=r"(r) : "f"(hi), "f"(lo));
    return r;
}

__device__ __forceinline__ void mma_f16(float c[4], const uint32_t a[4], uint32_t b0, uint32_t b1) {
    asm volatile(
        "mma.sync.aligned.m16n8k16.row.col.f32.f16.f16.f32 "
        "{%0,%1,%2,%3}, {%4,%5,%6,%7}, {%8,%9}, {%0,%1,%2,%3};\n"
        : "+f"(c[0]), "+f"(c[1]), "+f"(c[2]), "+f"(c[3])
        : "r"(a[0]), "r"(a[1]), "r"(a[2]), "r"(a[3]), "r"(b0), "r"(b1));
}

#define LDM_X4(r, a) \
    asm volatile("ldmatrix.sync.aligned.m8n8.x4.shared.b16 {%0,%1,%2,%3}, [%4];" \
        : "=r"((r)[0]), "=r"((r)[1]), "=r"((r)[2]), "=r"((r)[3]) : "r"(a))

__device__ __forceinline__ void cp_async16(uint32_t saddr, const void* gptr) {
    asm volatile("cp.async.cg.shared.global [%0], [%1], 16;\n" :: "r"(saddr), "l"(gptr));
}
__device__ __forceinline__ void cp_commit() { asm volatile("cp.async.commit_group;\n"); }
__device__ __forceinline__ void cp_wait0()  { asm volatile("cp.async.wait_group 0;\n" ::: "memory"); }

// ---- mbarrier helpers ----
#define MBAR_INIT(a, c) \
    asm volatile("mbarrier.init.shared.b64 [%0], %1;" :: "r"(a), "r"(c) : "memory")

__device__ __forceinline__ void mbar_arrive(uint32_t a) {
    asm volatile("mbarrier.arrive.shared.b64 _, [%0];" :: "r"(a) : "memory");
}
// .noinc REQUIRED (R10 hang: non-noinc bumps the expected count first)
__device__ __forceinline__ void cpasync_mbar_arrive(uint32_t a) {
    asm volatile("cp.async.mbarrier.arrive.noinc.shared.b64 [%0];" :: "r"(a) : "memory");
}

#define MBAR_WAIT(mb, ph) do { \
    uint32_t _m = (mb), _p = (ph), _d; \
    asm volatile("{ .reg .pred p; mbarrier.try_wait.parity.acquire.cta.shared::cta.b64 p, [%1], %2; selp.b32 %0, 1, 0, p; }" \
        : "=r"(_d) : "r"(_m), "r"(_p) : "memory"); \
    if (!_d) { \
        asm volatile("{ .reg .pred P1; WL_%=: mbarrier.try_wait.parity.acquire.cta.shared::cta.b64 P1, [%0], %1, 0x989680; @P1 bra.uni WD_%=; bra.uni WL_%=; WD_%=: }" \
            :: "r"(_m), "r"(_p) : "memory"); \
    } } while (0)

__device__ __forceinline__ float silu(float x) { return x / (1.0f + __expf(-x)); }

// setup: zero out + convert weights (one launch)
__global__ void setup_kernel(const float* __restrict__ W1,
                             const float* __restrict__ W2,
                             float* __restrict__ out, int n_out) {
    int i = blockIdx.x * blockDim.x + threadIdx.x;
    if (i < n_out) out[i] = 0.0f;
    if (i < 256 * 1024 / 2) g_W1h[i] = pack_f16x2(W1[2 * i], W1[2 * i + 1]);
    if (i < 256 * 256 / 2)  g_W2h[i] = pack_f16x2(W2[2 * i], W2[2 * i + 1]);
}

__global__ void __launch_bounds__(NTHREADS, 1)
fused_psm_kernel(const float* __restrict__ ps,
                 const int*   __restrict__ numbers,
                 const int*   __restrict__ batch,
                 const float* __restrict__ Wcomp,
                 const float* __restrict__ Wpsl,
                 const float* __restrict__ Wout,
                 float* __restrict__ out) {
    extern __shared__ char smem[];
    const uint32_t sbase = (uint32_t)__cvta_generic_to_shared(smem);
    float* sWpsl = (float*)(smem + OFF_WPSL);
    float* sWout = (float*)(smem + OFF_WOUT);
    float* sAtom = (float*)(smem + OFF_SATOM);

    const uint32_t mbR = sbase + OFF_MBAR;        // ready (A sts + B cp.async): +0, +8
    const uint32_t mbF = sbase + OFF_MBAR + 16;   // free  (consumers done):     +16, +24

    const int tid  = threadIdx.x;
    const int lane = tid & 31;
    const int w    = tid >> 5;
    const int g    = lane >> 2;
    const int t    = lane & 3;
    const int wm   = w & 3;    // rows wm*32..+31
    const int wn   = w >> 2;   // cols wn*64..+63
    const long tileBase = (long)blockIdx.x * M_TILE;

    // ldmatrix lane geometry
    const int lr = lane & 7;
    const uint32_t aAddr0 = sbase + OFF_A +
        (uint32_t)((wm * 32 + ((lane >> 3) & 1) * 8 + lr) * A_ROW_B + (lane >> 4) * 16);
    const uint32_t hAddr0 = sbase + OFF_H1 +
        (uint32_t)((wm * 32 + ((lane >> 3) & 1) * 8 + lr) * H1_ROW_B + (lane >> 4) * 16);
    const uint32_t bAddr0 = sbase + OFF_B +
        (uint32_t)((wn * 64 + (lane >> 4) * 8 + lr) * B_ROW_B + ((lane >> 3) & 1) * 16);

    if (tid < 256) sWout[tid] = Wout[tid];
    if (tid == 0) {
        MBAR_INIT(mbR + 0, 2 * NTHREADS);
        MBAR_INIT(mbR + 8, 2 * NTHREADS);
        MBAR_INIT(mbF + 0, NTHREADS);
        MBAR_INIT(mbF + 8, NTHREADS);
    }
    for (int i = tid; i < 1024; i += NTHREADS) sWpsl[i] = Wpsl[i];
    // sWpsl + mbarrier.init must be globally visible before prologue (R6 lesson).
    __syncthreads();

    // producer mapping: thread owns row=tid>>2 (0..127), 16 consecutive k at (tid&3)*16
    const int prow = tid >> 2;
    const int pt4  = tid & 3;
    const bool pvalid = (tileBase + prow) < (long)N_ATOMS;
    const float* pSrc = ps + (tileBase + prow) * (long)N_FEAT + pt4 * 16;
    const uint32_t aStore = sbase + OFF_A + (uint32_t)(prow * A_ROW_B + pt4 * 32);

    float acc[2][8][4];
#pragma unroll
    for (int mt = 0; mt < 2; mt++)
#pragma unroll
        for (int nt = 0; nt < 8; nt++)
#pragma unroll
            for (int c = 0; c < 4; c++) acc[mt][nt][c] = 0.0f;

    float psl = 0.0f;
    float rg[16];

    auto ldg_A = [&](int kc) {
        if (pvalid) {
            const float4* p = (const float4*)(pSrc + kc * 64);
#pragma unroll
            for (int j = 0; j < 4; j++) {
                float4 v = p[j];
                rg[4 * j] = v.x; rg[4 * j + 1] = v.y; rg[4 * j + 2] = v.z; rg[4 * j + 3] = v.w;
            }
        } else {
#pragma unroll
            for (int j = 0; j < 16; j++) rg[j] = 0.0f;
        }
    };
    auto sts_A = [&](int b) {
        uint32_t pk[8];
#pragma unroll
        for (int j = 0; j < 8; j++) pk[j] = pack_f16x2(rg[2 * j], rg[2 * j + 1]);
        uint32_t d = aStore + b * A_BUF_B;
        asm volatile("st.shared.v4.b32 [%0], {%1,%2,%3,%4};" :: "r"(d),
                     "r"(pk[0]), "r"(pk[1]), "r"(pk[2]), "r"(pk[3]));
        asm volatile("st.shared.v4.b32 [%0], {%1,%2,%3,%4};" :: "r"(d + 16),
                     "r"(pk[4]), "r"(pk[5]), "r"(pk[6]), "r"(pk[7]));
    };
    auto psl_acc = [&](int kc) {
        const float* wp = sWpsl + kc * 64 + pt4 * 16;
#pragma unroll
        for (int j = 0; j < 16; j++) psl += rg[j] * wp[j];
    };
    auto load_B1 = [&](int kc, int b) {
#pragma unroll
        for (int j = 0; j < 4; j++) {
            int idx = tid + j * NTHREADS;          // 0..2047
            int row = idx >> 3, c8 = idx & 7;
            uint32_t dst = sbase + OFF_B + b * B_BUF_B + row * B_ROW_B + c8 * 16;
            cp_async16(dst, &g_W1h[row * 512 + kc * 32 + c8 * 4]);
        }
        cp_commit();
    };
    auto load_B2 = [&](int c2, int b) {
#pragma unroll
        for (int j = 0; j < 4; j++) {
            int idx = tid + j * NTHREADS;
            int row = idx >> 3, c8 = idx & 7;
            uint32_t dst = sbase + OFF_B + b * B_BUF_B + row * B_ROW_B + c8 * 16;
            cp_async16(dst, &g_W2h[row * 128 + c2 * 32 + c8 * 4]);
        }
        cp_commit();
    };

    auto mma_chunk = [&](uint32_t aA, uint32_t bA, int rstride) {
#pragma unroll
        for (int ks = 0; ks < 4; ks++) {
            uint32_t a0[4], a1[4];
            LDM_X4(a0, aA + ks * 32);
            LDM_X4(a1, aA + ks * 32 + 16 * rstride);
#pragma unroll
            for (int np = 0; np < 4; np++) {
                uint32_t bb[4];
                LDM_X4(bb, bA + ks * 32 + np * (16 * B_ROW_B));
                mma_f16(acc[0][2 * np],     a0, bb[0], bb[1]);
                mma_f16(acc[0][2 * np + 1], a0, bb[2], bb[3]);
                mma_f16(acc[1][2 * np],     a1, bb[0], bb[1]);
                mma_f16(acc[1][2 * np + 1], a1, bb[2], bb[3]);
            }
        }
    };

    // ---- prologue: chunk 0 staged + signaled; chunk 1 A in regs ----
    ldg_A(0);
    load_B1(0, 0);
    cpasync_mbar_arrive(mbR + 0);      // B(0) half of readiness
    sts_A(0);
    mbar_arrive(mbR + 0);              // A(0) half of readiness
    psl_acc(0);
    ldg_A(1);

    // =============== GEMM1 (mbarrier pipeline, warps may skew) ===============
    for (int kc = 0; kc < CHUNKS1; kc++) {
        const int buf = kc & 1;
        const int ph  = (kc >> 1) & 1;

        // --- produce chunk kc+1 into buf^1 ---
        if (kc + 1 < CHUNKS1) {
            if (kc + 1 >= 2) {
                // wait until all readers of chunk kc-1 (same buf^1) are done
                MBAR_WAIT(mbF + (buf ^ 1) * 8, (((kc + 1) >> 1) & 1) ^ 1);
            }
            sts_A(buf ^ 1);                       // A(kc+1), regs from prev iter
            mbar_arrive(mbR + (buf ^ 1) * 8);
            psl_acc(kc + 1);
            load_B1(kc + 1, buf ^ 1);
            cpasync_mbar_arrive(mbR + (buf ^ 1) * 8);
            if (kc + 2 < CHUNKS1) ldg_A(kc + 2);
        }

        // --- consume chunk kc (single fused ready-wait) ---
        MBAR_WAIT(mbR + buf * 8, ph);
        mma_chunk(aAddr0 + buf * A_BUF_B, bAddr0 + buf * B_BUF_B, A_ROW_B);
        mbar_arrive(mbF + buf * 8);               // this thread done reading buf
    }
    __syncthreads();   // all GEMM1 reads done before h1 overwrites A alias

    // GEMM2 B chunk 0 prefetch overlaps h1 write
    load_B2(0, 0);

    // psl reduce (4 threads per row share a warp quad)
    psl += __shfl_xor_sync(0xffffffffu, psl, 1);
    psl += __shfl_xor_sync(0xffffffffu, psl, 2);
    if (pt4 == 0) sAtom[prow] = psl;

    // h1 = fp16(silu(acc)) -> row-major SMEM; reset acc
#pragma unroll
    for (int mt = 0; mt < 2; mt++) {
        int row = wm * 32 + mt * 16 + g;
#pragma unroll
        for (int nt = 0; nt < 8; nt++) {
            int col = wn * 64 + nt * 8 + 2 * t;
            *(uint32_t*)(smem + OFF_H1 + row * H1_ROW_B + col * 2) =
                pack_f16x2(silu(acc[mt][nt][0]), silu(acc[mt][nt][1]));
            *(uint32_t*)(smem + OFF_H1 + (row + 8) * H1_ROW_B + col * 2) =
                pack_f16x2(silu(acc[mt][nt][2]), silu(acc[mt][nt][3]));
            acc[mt][nt][0] = acc[mt][nt][1] = acc[mt][nt][2] = acc[mt][nt][3] = 0.0f;
        }
    }

    // =============== GEMM2: acc += h1 x W2^T (simple barrier pipeline) ========
    for (int c = 0; c < CHUNKS2; c++) {
        const int buf = c & 1;
        cp_wait0();
        __syncthreads();   // B2(c) arrived; h1 writes visible (c==0)
        if (c + 1 < CHUNKS2) load_B2(c + 1, buf ^ 1);

        mma_chunk(hAddr0 + c * 128, bAddr0 + buf * B_BUF_B, H1_ROW_B);
    }

    // ---- epilogue: psnn = silu(h2) . Wout ----
#pragma unroll
    for (int mt = 0; mt < 2; mt++) {
        float p0 = 0.0f, p1 = 0.0f;
#pragma unroll
        for (int nt = 0; nt < 8; nt++) {
            int col = wn * 64 + nt * 8 + 2 * t;
            float w0 = sWout[col], w1 = sWout[col + 1];
            p0 += silu(acc[mt][nt][0]) * w0 + silu(acc[mt][nt][1]) * w1;
            p1 += silu(acc[mt][nt][2]) * w0 + silu(acc[mt][nt][3]) * w1;
        }
        p0 += __shfl_xor_sync(0xffffffffu, p0, 1);
        p0 += __shfl_xor_sync(0xffffffffu, p0, 2);
        p1 += __shfl_xor_sync(0xffffffffu, p1, 1);
        p1 += __shfl_xor_sync(0xffffffffu, p1, 2);
        if (t == 0) {
            atomicAdd(&sAtom[wm * 32 + mt * 16 + g], p0);
            atomicAdd(&sAtom[wm * 32 + mt * 16 + 8 + g], p1);
        }
    }
    __syncthreads();

    if (tid < M_TILE) {
        long a = tileBase + tid;
        if (a < N_ATOMS) {
            float v = sAtom[tid] + Wcomp[numbers[a]];
            atomicAdd(&out[batch[a]], v);
        }
    }
}

extern "C" void kernel_launch(void* const* d_in, const int* in_sizes, int n_in,
                              void* d_out, int out_size) {
    const float* ps      = (const float*)d_in[0];
    const int*   numbers = (const int*)  d_in[1];
    const int*   batch   = (const int*)  d_in[2];
    const float* Wcomp   = (const float*)d_in[3];
    const float* Wpsl    = (const float*)d_in[4];
    const float* W1      = (const float*)d_in[5];
    const float* W2      = (const float*)d_in[6];
    const float* Wout    = (const float*)d_in[7];
    float* out = (float*)d_out;

    cudaFuncSetAttribute(fused_psm_kernel,
                         cudaFuncAttributeMaxDynamicSharedMemorySize, SMEM_BYTES);

    setup_kernel<<<(256 * 1024 / 2 + 255) / 256, 256>>>(W1, W2, out, out_size);

    int grid = (N_ATOMS + M_TILE - 1) / M_TILE;  // 1563
    fused_psm_kernel<<<grid, NTHREADS, SMEM_BYTES>>>(
        ps, numbers, batch, Wcomp, Wpsl, Wout, out);
}

// round 17
// speedup vs baseline: 1.6772x; 1.0186x over previous
#include <cuda_runtime.h>
#include <cstdint>

#define N_ATOMS  200000
#define N_FEAT   1024
#define N_STRUCT 2000
#define NTHREADS 768
#define M_TILE   96
#define CHUNKS1  16      // K=1024 / 64
#define CHUNKS2  4       // K=256  / 64

// ---- SMEM layout (bytes). fp16 operand tiles, rows padded to 144B (64k + 8 pad halves)
#define A_ROW_B    144
#define B_ROW_B    144
#define H1_ROW_B   528                   // 256 + 8 pad halves
#define A_BUF_B    13824                 // 96*144
#define B_BUF_B    36864                 // 256*144
#define OFF_B      0                     // 2 bufs -> 73728
#define OFF_A      73728                 // 2 bufs 27648, aliased inside h1 region
#define OFF_H1     73728                 // 96*528 = 50688 -> ends 124416
#define OFF_WPSL   124416                // 4096
#define OFF_WOUT   128512                // 1024
#define OFF_SATOM  129536                // 512 (96 used)
#define OFF_MBAR   130048                // 4 x 8B: R0 R1 F0 F1
#define SMEM_BYTES 130112

// weights pre-converted to fp16 (rn), natural [n][k] layout, packed as uint32 pairs
__device__ __align__(16) uint32_t g_W1h[256 * 1024 / 2];
__device__ __align__(16) uint32_t g_W2h[256 * 256 / 2];

__device__ __forceinline__ uint32_t pack_f16x2(float lo, float hi) {
    uint32_t r;
    asm("cvt.rn.f16x2.f32 %0, %1, %2;" : "=r"(r) : "f"(hi), "f"(lo));
    return r;
}

__device__ __forceinline__ void mma_f16(float c[4], const uint32_t a[4], uint32_t b0, uint32_t b1) {
    asm volatile(
        "mma.sync.aligned.m16n8k16.row.col.f32.f16.f16.f32 "
        "{%0,%1,%2,%3}, {%4,%5,%6,%7}, {%8,%9}, {%0,%1,%2,%3};\n"
        : "+f"(c[0]), "+f"(c[1]), "+f"(c[2]), "+f"(c[3])
        : "r"(a[0]), "r"(a[1]), "r"(a[2]), "r"(a[3]), "r"(b0), "r"(b1));
}

#define LDM_X4(r, a) \
    asm volatile("ldmatrix.sync.aligned.m8n8.x4.shared.b16 {%0,%1,%2,%3}, [%4];" \
        : "=r"((r)[0]), "=r"((r)[1]), "=r"((r)[2]), "=r"((r)[3]) : "r"(a))

__device__ __forceinline__ void cp_async16(uint32_t saddr, const void* gptr) {
    asm volatile("cp.async.cg.shared.global [%0], [%1], 16;\n" :: "r"(saddr), "l"(gptr));
}
__device__ __forceinline__ void cp_commit() { asm volatile("cp.async.commit_group;\n"); }
__device__ __forceinline__ void cp_wait0()  { asm volatile("cp.async.wait_group 0;\n" ::: "memory"); }

// ---- mbarrier helpers ----
#define MBAR_INIT(a, c) \
    asm volatile("mbarrier.init.shared.b64 [%0], %1;" :: "r"(a), "r"(c) : "memory")

__device__ __forceinline__ void mbar_arrive(uint32_t a) {
    asm volatile("mbarrier.arrive.shared.b64 _, [%0];" :: "r"(a) : "memory");
}
// .noinc REQUIRED (R10 hang: non-noinc bumps the expected count first)
__device__ __forceinline__ void cpasync_mbar_arrive(uint32_t a) {
    asm volatile("cp.async.mbarrier.arrive.noinc.shared.b64 [%0];" :: "r"(a) : "memory");
}

#define MBAR_WAIT(mb, ph) do { \
    uint32_t _m = (mb), _p = (ph), _d; \
    asm volatile("{ .reg .pred p; mbarrier.try_wait.parity.acquire.cta.shared::cta.b64 p, [%1], %2; selp.b32 %0, 1, 0, p; }" \
        : "=r"(_d) : "r"(_m), "r"(_p) : "memory"); \
    if (!_d) { \
        asm volatile("{ .reg .pred P1; WL_%=: mbarrier.try_wait.parity.acquire.cta.shared::cta.b64 P1, [%0], %1, 0x989680; @P1 bra.uni WD_%=; bra.uni WL_%=; WD_%=: }" \
            :: "r"(_m), "r"(_p) : "memory"); \
    } } while (0)

__device__ __forceinline__ float silu(float x) { return x / (1.0f + __expf(-x)); }

// setup: zero out + convert weights (one launch)
__global__ void setup_kernel(const float* __restrict__ W1,
                             const float* __restrict__ W2,
                             float* __restrict__ out, int n_out) {
    int i = blockIdx.x * blockDim.x + threadIdx.x;
    if (i < n_out) out[i] = 0.0f;
    if (i < 256 * 1024 / 2) g_W1h[i] = pack_f16x2(W1[2 * i], W1[2 * i + 1]);
    if (i < 256 * 256 / 2)  g_W2h[i] = pack_f16x2(W2[2 * i], W2[2 * i + 1]);
}

__global__ void __launch_bounds__(NTHREADS, 1)
fused_psm_kernel(const float* __restrict__ ps,
                 const int*   __restrict__ numbers,
                 const int*   __restrict__ batch,
                 const float* __restrict__ Wcomp,
                 const float* __restrict__ Wpsl,
                 const float* __restrict__ Wout,
                 float* __restrict__ out) {
    extern __shared__ char smem[];
    const uint32_t sbase = (uint32_t)__cvta_generic_to_shared(smem);
    float* sWpsl = (float*)(smem + OFF_WPSL);
    float* sWout = (float*)(smem + OFF_WOUT);
    float* sAtom = (float*)(smem + OFF_SATOM);

    const uint32_t mbR = sbase + OFF_MBAR;        // ready (A sts + B cp.async): +0, +8
    const uint32_t mbF = sbase + OFF_MBAR + 16;   // free  (consumers done):     +16, +24

    const int tid  = threadIdx.x;
    const int lane = tid & 31;
    const int w    = tid >> 5;
    const int g    = lane >> 2;
    const int t    = lane & 3;
    const int wm   = w % 3;    // M-group: rows wm*32..+31
    const int wn   = w / 3;    // N-group: cols wn*32..+31
    const long tileBase = (long)blockIdx.x * M_TILE;

    // ldmatrix lane geometry
    const int lr = lane & 7;
    const uint32_t aAddr0 = sbase + OFF_A +
        (uint32_t)((wm * 32 + ((lane >> 3) & 1) * 8 + lr) * A_ROW_B + (lane >> 4) * 16);
    const uint32_t hAddr0 = sbase + OFF_H1 +
        (uint32_t)((wm * 32 + ((lane >> 3) & 1) * 8 + lr) * H1_ROW_B + (lane >> 4) * 16);
    const uint32_t bAddr0 = sbase + OFF_B +
        (uint32_t)((wn * 32 + (lane >> 4) * 8 + lr) * B_ROW_B + ((lane >> 3) & 1) * 16);

    if (tid < 256) sWout[tid] = Wout[tid];
    if (tid == 0) {
        MBAR_INIT(mbR + 0, 2 * NTHREADS);
        MBAR_INIT(mbR + 8, 2 * NTHREADS);
        MBAR_INIT(mbF + 0, NTHREADS);
        MBAR_INIT(mbF + 8, NTHREADS);
    }
    for (int i = tid; i < 1024; i += NTHREADS) sWpsl[i] = Wpsl[i];
    // sWpsl + mbarrier.init must be globally visible before prologue (R6 lesson).
    __syncthreads();

    // producer mapping: thread owns row=tid>>3 (0..95), 8 consecutive k at (tid&7)*8
    const int prow = tid >> 3;
    const int pt8  = tid & 7;
    const bool pvalid = (tileBase + prow) < (long)N_ATOMS;
    const float* pSrc = ps + (tileBase + prow) * (long)N_FEAT + pt8 * 8;
    const uint32_t aStore = sbase + OFF_A + (uint32_t)(prow * A_ROW_B + pt8 * 16);

    float acc[2][4][4];
#pragma unroll
    for (int mt = 0; mt < 2; mt++)
#pragma unroll
        for (int nt = 0; nt < 4; nt++)
#pragma unroll
            for (int c = 0; c < 4; c++) acc[mt][nt][c] = 0.0f;

    float psl = 0.0f;
    float rg[8];

    auto ldg_A = [&](int kc) {
        if (pvalid) {
            const float4* p = (const float4*)(pSrc + kc * 64);
            float4 v0 = p[0], v1 = p[1];
            rg[0] = v0.x; rg[1] = v0.y; rg[2] = v0.z; rg[3] = v0.w;
            rg[4] = v1.x; rg[5] = v1.y; rg[6] = v1.z; rg[7] = v1.w;
        } else {
#pragma unroll
            for (int j = 0; j < 8; j++) rg[j] = 0.0f;
        }
    };
    auto sts_A = [&](int b) {
        uint32_t pk[4];
#pragma unroll
        for (int j = 0; j < 4; j++) pk[j] = pack_f16x2(rg[2 * j], rg[2 * j + 1]);
        asm volatile("st.shared.v4.b32 [%0], {%1,%2,%3,%4};" :: "r"(aStore + b * A_BUF_B),
                     "r"(pk[0]), "r"(pk[1]), "r"(pk[2]), "r"(pk[3]));
    };
    auto psl_acc = [&](int kc) {
        const float* wp = sWpsl + kc * 64 + pt8 * 8;
#pragma unroll
        for (int j = 0; j < 8; j++) psl += rg[j] * wp[j];
    };
    auto load_B1 = [&](int kc, int b) {
#pragma unroll
        for (int j = 0; j < 3; j++) {
            int idx = tid + j * NTHREADS;          // 0..2303, need 0..2047
            if (idx < 2048) {
                int row = idx >> 3, c8 = idx & 7;
                uint32_t dst = sbase + OFF_B + b * B_BUF_B + row * B_ROW_B + c8 * 16;
                cp_async16(dst, &g_W1h[row * 512 + kc * 32 + c8 * 4]);
            }
        }
        cp_commit();
    };
    auto load_B2 = [&](int c2, int b) {
#pragma unroll
        for (int j = 0; j < 3; j++) {
            int idx = tid + j * NTHREADS;
            if (idx < 2048) {
                int row = idx >> 3, c8 = idx & 7;
                uint32_t dst = sbase + OFF_B + b * B_BUF_B + row * B_ROW_B + c8 * 16;
                cp_async16(dst, &g_W2h[row * 128 + c2 * 32 + c8 * 4]);
            }
        }
        cp_commit();
    };

    auto mma_chunk = [&](uint32_t aA, uint32_t bA, int rstride) {
#pragma unroll
        for (int ks = 0; ks < 4; ks++) {
            uint32_t a0[4], a1[4];
            LDM_X4(a0, aA + ks * 32);
            LDM_X4(a1, aA + ks * 32 + 16 * rstride);
#pragma unroll
            for (int np = 0; np < 2; np++) {
                uint32_t bb[4];
                LDM_X4(bb, bA + ks * 32 + np * (16 * B_ROW_B));
                mma_f16(acc[0][2 * np],     a0, bb[0], bb[1]);
                mma_f16(acc[0][2 * np + 1], a0, bb[2], bb[3]);
                mma_f16(acc[1][2 * np],     a1, bb[0], bb[1]);
                mma_f16(acc[1][2 * np + 1], a1, bb[2], bb[3]);
            }
        }
    };

    // ---- prologue: chunk 0 staged + signaled; chunk 1 A in regs ----
    ldg_A(0);
    load_B1(0, 0);
    cpasync_mbar_arrive(mbR + 0);      // B(0) half of readiness
    sts_A(0);
    mbar_arrive(mbR + 0);              // A(0) half of readiness
    psl_acc(0);
    ldg_A(1);

    // =============== GEMM1 (mbarrier pipeline, warps may skew) ===============
    for (int kc = 0; kc < CHUNKS1; kc++) {
        const int buf = kc & 1;
        const int ph  = (kc >> 1) & 1;

        // --- produce chunk kc+1 into buf^1 ---
        if (kc + 1 < CHUNKS1) {
            if (kc + 1 >= 2) {
                // wait until all readers of chunk kc-1 (same buf^1) are done
                MBAR_WAIT(mbF + (buf ^ 1) * 8, (((kc + 1) >> 1) & 1) ^ 1);
            }
            sts_A(buf ^ 1);                       // A(kc+1), regs from prev iter
            mbar_arrive(mbR + (buf ^ 1) * 8);
            psl_acc(kc + 1);
            load_B1(kc + 1, buf ^ 1);
            cpasync_mbar_arrive(mbR + (buf ^ 1) * 8);
            if (kc + 2 < CHUNKS1) ldg_A(kc + 2);
        }

        // --- consume chunk kc (single fused ready-wait) ---
        MBAR_WAIT(mbR + buf * 8, ph);
        mma_chunk(aAddr0 + buf * A_BUF_B, bAddr0 + buf * B_BUF_B, A_ROW_B);
        mbar_arrive(mbF + buf * 8);               // this thread done reading buf
    }
    __syncthreads();   // all GEMM1 reads done before h1 overwrites A alias

    // GEMM2 B chunk 0 prefetch overlaps h1 write
    load_B2(0, 0);

    // psl reduce (8 threads per row, adjacent lanes)
    psl += __shfl_xor_sync(0xffffffffu, psl, 1);
    psl += __shfl_xor_sync(0xffffffffu, psl, 2);
    psl += __shfl_xor_sync(0xffffffffu, psl, 4);
    if (pt8 == 0) sAtom[prow] = psl;

    // h1 = fp16(silu(acc)) -> row-major SMEM; reset acc
#pragma unroll
    for (int mt = 0; mt < 2; mt++) {
        int row = wm * 32 + mt * 16 + g;
#pragma unroll
        for (int nt = 0; nt < 4; nt++) {
            int col = wn * 32 + nt * 8 + 2 * t;
            *(uint32_t*)(smem + OFF_H1 + row * H1_ROW_B + col * 2) =
                pack_f16x2(silu(acc[mt][nt][0]), silu(acc[mt][nt][1]));
            *(uint32_t*)(smem + OFF_H1 + (row + 8) * H1_ROW_B + col * 2) =
                pack_f16x2(silu(acc[mt][nt][2]), silu(acc[mt][nt][3]));
            acc[mt][nt][0] = acc[mt][nt][1] = acc[mt][nt][2] = acc[mt][nt][3] = 0.0f;
        }
    }

    // =============== GEMM2: acc += h1 x W2^T (simple barrier pipeline) ========
    for (int c = 0; c < CHUNKS2; c++) {
        const int buf = c & 1;
        cp_wait0();
        __syncthreads();   // B2(c) arrived; h1 writes visible (c==0)
        if (c + 1 < CHUNKS2) load_B2(c + 1, buf ^ 1);

        mma_chunk(hAddr0 + c * 128, bAddr0 + buf * B_BUF_B, H1_ROW_B);
    }

    // ---- epilogue: psnn = silu(h2) . Wout ----
#pragma unroll
    for (int mt = 0; mt < 2; mt++) {
        float p0 = 0.0f, p1 = 0.0f;
#pragma unroll
        for (int nt = 0; nt < 4; nt++) {
            int col = wn * 32 + nt * 8 + 2 * t;
            float w0 = sWout[col], w1 = sWout[col + 1];
            p0 += silu(acc[mt][nt][0]) * w0 + silu(acc[mt][nt][1]) * w1;
            p1 += silu(acc[mt][nt][2]) * w0 + silu(acc[mt][nt][3]) * w1;
        }
        p0 += __shfl_xor_sync(0xffffffffu, p0, 1);
        p0 += __shfl_xor_sync(0xffffffffu, p0, 2);
        p1 += __shfl_xor_sync(0xffffffffu, p1, 1);
        p1 += __shfl_xor_sync(0xffffffffu, p1, 2);
        if (t == 0) {
            atomicAdd(&sAtom[wm * 32 + mt * 16 + g], p0);
            atomicAdd(&sAtom[wm * 32 + mt * 16 + 8 + g], p1);
        }
    }
    __syncthreads();

    if (tid < M_TILE) {
        long a = tileBase + tid;
        if (a < N_ATOMS) {
            float v = sAtom[tid] + Wcomp[numbers[a]];
            atomicAdd(&out[batch[a]], v);
        }
    }
}

extern "C" void kernel_launch(void* const* d_in, const int* in_sizes, int n_in,
                              void* d_out, int out_size) {
    const float* ps      = (const float*)d_in[0];
    const int*   numbers = (const int*)  d_in[1];
    const int*   batch   = (const int*)  d_in[2];
    const float* Wcomp   = (const float*)d_in[3];
    const float* Wpsl    = (const float*)d_in[4];
    const float* W1      = (const float*)d_in[5];
    const float* W2      = (const float*)d_in[6];
    const float* Wout    = (const float*)d_in[7];
    float* out = (float*)d_out;

    cudaFuncSetAttribute(fused_psm_kernel,
                         cudaFuncAttributeMaxDynamicSharedMemorySize, SMEM_BYTES);

    setup_kernel<<<(256 * 1024 / 2 + 255) / 256, 256>>>(W1, W2, out, out_size);

    int grid = (N_ATOMS + M_TILE - 1) / M_TILE;  // 2084
    fused_psm_kernel<<<grid, NTHREADS, SMEM_BYTES>>>(
        ps, numbers, batch, Wcomp, Wpsl, Wout, out);
}